// round 11
// baseline (speedup 1.0000x reference)
#include <cuda_runtime.h>
#include <cstdint>

// Problem constants
#define BSZ      256   // batch
#define TSTEPS   512   // time steps
#define HID      256   // hidden
#define G4       1024  // 4*H
#define GBGROUPS 8     // batch groups
#define GSLICES  16    // gate slices per group
#define NCTA     128   // GBGROUPS*GSLICES
#define BC       32    // batch per group
#define NU       16    // hidden units per slice per layer
#define NG       64    // gate rows per slice per layer (4*NU)
#define NTHREADS 128

// Persistent scratch (no cudaMalloc allowed) --------------------------------
__device__ float g_h0[2 * BSZ * HID];      // double buffered layer-0 hidden
__device__ float g_h1[2 * BSZ * HID];      // double buffered layer-1 hidden
__device__ float g_pp[BSZ * GSLICES];      // pred partials per slice
__device__ float g_losspart[GBGROUPS];     // per-group loss sums
__device__ int   g_bar[GBGROUPS];          // per-group barrier counters

// Shared memory layout (big float4-aligned arrays first) --------------------
struct SmemLayout {
    float w0t [256 * NG];   // Whh_l0 slice, [k][n] layout   64KB
    float w1it[256 * NG];   // Wih_l1 slice, [k][n]          64KB
    float w1ht[256 * NG];   // Whh_l1 slice, [k][n]          64KB
    float hT  [128 * 34];   // staged h chunk, [k][m], row padded to 34
    float gbuf[BC * NG];    // gates tile 32x64
    float c0s [BC * NU];    // cell state layer0
    float c1s [BC * NU];    // cell state layer1
    float h1S [BC * NU];    // h1_new slice (for pred partial)
    float predvS[BC];
    float wih0 [NG];        // W_ih_l0 column slice
    float bias0[NG];        // b_ih_l0 + b_hh_l0
    float bias1[NG];
    float woutS[NU];
    float lossS[BC];
    float boutv;
};

__device__ __forceinline__ float sigf(float x) {
    return 1.0f / (1.0f + __expf(-x));
}

__device__ __forceinline__ void group_barrier(int g, int target) {
    __threadfence();          // publish this thread's global writes
    __syncthreads();          // all threads' fences done
    if (threadIdx.x == 0) {
        atomicAdd(&g_bar[g], 1);
        while (((volatile int*)g_bar)[g] < target) { __nanosleep(32); }
    }
    __syncthreads();
}

// rank-1 style 4x4 FFMA update
#define MMA16()                                                                             \
    do {                                                                                    \
        acc[0][0] += a01.x * b4.x; acc[0][1] += a01.x * b4.y;                               \
        acc[0][2] += a01.x * b4.z; acc[0][3] += a01.x * b4.w;                               \
        acc[1][0] += a01.y * b4.x; acc[1][1] += a01.y * b4.y;                               \
        acc[1][2] += a01.y * b4.z; acc[1][3] += a01.y * b4.w;                               \
        acc[2][0] += a23.x * b4.x; acc[2][1] += a23.x * b4.y;                               \
        acc[2][2] += a23.x * b4.z; acc[2][3] += a23.x * b4.w;                               \
        acc[3][0] += a23.y * b4.x; acc[3][1] += a23.y * b4.y;                               \
        acc[3][2] += a23.y * b4.z; acc[3][3] += a23.y * b4.w;                               \
    } while (0)

// Init: zero counters/partials, seed h0/h1 with z ---------------------------
__global__ void init_kernel(const float* __restrict__ z) {
    int t = blockIdx.x * blockDim.x + threadIdx.x;
    if (t < BSZ * HID) {
        float v = z[t];
        g_h0[t] = v;   // buffer 0 is "cur" at step 0
        g_h1[t] = v;
    }
    if (t < BSZ * GSLICES) g_pp[t] = 0.0f;
    if (t < GBGROUPS) { g_bar[t] = 0; g_losspart[t] = 0.0f; }
}

__global__ __launch_bounds__(NTHREADS, 1)
void lstm_kernel(const float* __restrict__ seq,  const float* __restrict__ z,
                 const float* __restrict__ Wih0, const float* __restrict__ Whh0,
                 const float* __restrict__ bih0, const float* __restrict__ bhh0,
                 const float* __restrict__ Wih1, const float* __restrict__ Whh1,
                 const float* __restrict__ bih1, const float* __restrict__ bhh1,
                 const float* __restrict__ Wout, const float* __restrict__ boutp) {
    extern __shared__ __align__(16) char smraw[];
    SmemLayout& S = *reinterpret_cast<SmemLayout*>(smraw);

    const int tid   = threadIdx.x;
    const int g     = blockIdx.x / GSLICES;   // batch group
    const int s     = blockIdx.x % GSLICES;   // gate slice
    const int bbase = g * BC;
    const int ubase = s * NU;

    // ---- one-time weight load (transposed into [k][n]) ----
    for (int idx = tid; idx < NG * HID; idx += NTHREADS) {
        int nl   = idx >> 8;       // 0..63
        int k    = idx & 255;
        int grow = ((nl >> 4) << 8) + ubase + (nl & 15);  // q*256 + ubase + u
        S.w0t [k * NG + nl] = Whh0[grow * HID + k];
        S.w1it[k * NG + nl] = Wih1[grow * HID + k];
        S.w1ht[k * NG + nl] = Whh1[grow * HID + k];
    }
    for (int nl = tid; nl < NG; nl += NTHREADS) {
        int grow = ((nl >> 4) << 8) + ubase + (nl & 15);
        S.wih0 [nl] = Wih0[grow];                 // (4H,1) column
        S.bias0[nl] = bih0[grow] + bhh0[grow];
        S.bias1[nl] = bih1[grow] + bhh1[grow];
    }
    if (tid < NU)  S.woutS[tid] = Wout[ubase + tid];
    if (tid == 0)  S.boutv = boutp[0];
    for (int idx = tid; idx < BC * NU; idx += NTHREADS) {
        int m = idx >> 4, u = idx & 15;
        float v = z[(bbase + m) * HID + ubase + u];
        S.c0s[idx] = v;
        S.c1s[idx] = v;
    }
    __syncthreads();

    const int tm = tid >> 4, tn = tid & 15;
    const int m0 = tm * 4,   n0 = tn * 4;
    const int w  = tid >> 5, lane = tid & 31;
    float lossreg = 0.0f;

    for (int t = 0; t <= TSTEPS; ++t) {
        // ---- phase 1: assemble pred from partials; accumulate loss ----
        if (tid < BC) {
            float pv;
            if (t == 0) {
                pv = 0.0f;   // pred0 = zeros
            } else {
                pv = S.boutv;
                const float* pp = &g_pp[(bbase + tid) * GSLICES];
                #pragma unroll
                for (int q = 0; q < GSLICES; ++q) pv += __ldcg(pp + q);
            }
            S.predvS[tid] = pv;
            if (s == 0 && t > 0) {
                float d = __ldg(&seq[(bbase + tid) * TSTEPS + (t - 1)]) - pv;
                lossreg += d * d;
            }
        }
        __syncthreads();
        if (t == TSTEPS) break;

        const int cur = t & 1, nxt = cur ^ 1;
        float acc[4][4];

        // ---- phase 2: layer-0 gates GEMM (K=256) ----
        {
            float pvv[4];
            #pragma unroll
            for (int i = 0; i < 4; ++i) pvv[i] = S.predvS[m0 + i];
            #pragma unroll
            for (int j = 0; j < 4; ++j) {
                float b = S.bias0[n0 + j], wv = S.wih0[n0 + j];
                #pragma unroll
                for (int i = 0; i < 4; ++i) acc[i][j] = b + pvv[i] * wv;
            }
        }
        const float* h0cur = &g_h0[cur * BSZ * HID];
        for (int c = 0; c < 2; ++c) {
            #pragma unroll
            for (int mm = 0; mm < 8; ++mm) {        // stage hT[k][m]
                int m = w * 8 + mm;
                float4 v = __ldcg(reinterpret_cast<const float4*>(
                               h0cur + (bbase + m) * HID + c * 128) + lane);
                int kb = lane * 4;
                S.hT[(kb + 0) * 34 + m] = v.x;
                S.hT[(kb + 1) * 34 + m] = v.y;
                S.hT[(kb + 2) * 34 + m] = v.z;
                S.hT[(kb + 3) * 34 + m] = v.w;
            }
            __syncthreads();
            const float* wt = &S.w0t[(c * 128) * NG];
            #pragma unroll 8
            for (int k = 0; k < 128; ++k) {
                const float2* ap = reinterpret_cast<const float2*>(&S.hT[k * 34 + m0]);
                float2 a01 = ap[0], a23 = ap[1];
                float4 b4 = *reinterpret_cast<const float4*>(&wt[k * NG + n0]);
                MMA16();
            }
            __syncthreads();
        }
        #pragma unroll
        for (int i = 0; i < 4; ++i) {
            float4 r = make_float4(acc[i][0], acc[i][1], acc[i][2], acc[i][3]);
            *reinterpret_cast<float4*>(&S.gbuf[(m0 + i) * NG + n0]) = r;
        }
        __syncthreads();
        {   // layer-0 activations + write h0_new slice
            int u = tid & 15, mq = tid >> 4;
            float* h0nxt = &g_h0[nxt * BSZ * HID];
            #pragma unroll
            for (int r = 0; r < 4; ++r) {
                int m = mq * 4 + r;
                float gi = S.gbuf[m * NG + u];
                float gf = S.gbuf[m * NG + 16 + u];
                float gg = S.gbuf[m * NG + 32 + u];
                float go = S.gbuf[m * NG + 48 + u];
                float cv = S.c0s[m * NU + u];
                float cn = sigf(gf) * cv + sigf(gi) * tanhf(gg);
                float hn = sigf(go) * tanhf(cn);
                S.c0s[m * NU + u] = cn;
                h0nxt[(bbase + m) * HID + ubase + u] = hn;
            }
        }
        group_barrier(g, t * 32 + 16);   // barrier A: h0_new published

        // ---- phase 3: layer-1 gates GEMM (K=512 = h0_new ++ h1) ----
        #pragma unroll
        for (int j = 0; j < 4; ++j) {
            float b = S.bias1[n0 + j];
            #pragma unroll
            for (int i = 0; i < 4; ++i) acc[i][j] = b;
        }
        const float* h0n = &g_h0[nxt * BSZ * HID];
        const float* h1c = &g_h1[cur * BSZ * HID];
        for (int c = 0; c < 4; ++c) {
            const float* src = (c < 2) ? h0n : h1c;
            int col = (c & 1) * 128;
            #pragma unroll
            for (int mm = 0; mm < 8; ++mm) {
                int m = w * 8 + mm;
                float4 v = __ldcg(reinterpret_cast<const float4*>(
                               src + (bbase + m) * HID + col) + lane);
                int kb = lane * 4;
                S.hT[(kb + 0) * 34 + m] = v.x;
                S.hT[(kb + 1) * 34 + m] = v.y;
                S.hT[(kb + 2) * 34 + m] = v.z;
                S.hT[(kb + 3) * 34 + m] = v.w;
            }
            __syncthreads();
            const float* wt = (c < 2) ? &S.w1it[(c * 128) * NG]
                                      : &S.w1ht[((c - 2) * 128) * NG];
            #pragma unroll 8
            for (int k = 0; k < 128; ++k) {
                const float2* ap = reinterpret_cast<const float2*>(&S.hT[k * 34 + m0]);
                float2 a01 = ap[0], a23 = ap[1];
                float4 b4 = *reinterpret_cast<const float4*>(&wt[k * NG + n0]);
                MMA16();
            }
            __syncthreads();
        }
        #pragma unroll
        for (int i = 0; i < 4; ++i) {
            float4 r = make_float4(acc[i][0], acc[i][1], acc[i][2], acc[i][3]);
            *reinterpret_cast<float4*>(&S.gbuf[(m0 + i) * NG + n0]) = r;
        }
        __syncthreads();
        {   // layer-1 activations; write h1_new slice + stage for pred partial
            int u = tid & 15, mq = tid >> 4;
            float* h1nxt = &g_h1[nxt * BSZ * HID];
            #pragma unroll
            for (int r = 0; r < 4; ++r) {
                int m = mq * 4 + r;
                float gi = S.gbuf[m * NG + u];
                float gf = S.gbuf[m * NG + 16 + u];
                float gg = S.gbuf[m * NG + 32 + u];
                float go = S.gbuf[m * NG + 48 + u];
                float cv = S.c1s[m * NU + u];
                float cn = sigf(gf) * cv + sigf(gi) * tanhf(gg);
                float hn = sigf(go) * tanhf(cn);
                S.c1s[m * NU + u] = cn;
                S.h1S[m * NU + u] = hn;
                h1nxt[(bbase + m) * HID + ubase + u] = hn;
            }
        }
        __syncthreads();
        if (tid < BC) {   // pred partial for this slice (deterministic)
            float pp = 0.0f;
            #pragma unroll
            for (int u2 = 0; u2 < NU; ++u2) pp += S.h1S[tid * NU + u2] * S.woutS[u2];
            g_pp[(bbase + tid) * GSLICES + s] = pp;
        }
        group_barrier(g, t * 32 + 32);   // barrier B: h1_new + partials published
    }

    // ---- per-group loss reduction (fixed order, deterministic) ----
    if (s == 0) {
        if (tid < BC) S.lossS[tid] = lossreg;
        __syncthreads();
        if (tid == 0) {
            float sum = 0.0f;
            for (int i = 0; i < BC; ++i) sum += S.lossS[i];
            g_losspart[g] = sum;
        }
    }
}

__global__ void finish_kernel(float* __restrict__ out) {
    float sum = 0.0f;
    for (int i = 0; i < GBGROUPS; ++i) sum += g_losspart[i];
    out[0] = sum / (float)(BSZ * TSTEPS);
}

extern "C" void kernel_launch(void* const* d_in, const int* in_sizes, int n_in,
                              void* d_out, int out_size) {
    const float* seq  = (const float*)d_in[0];   // (B,T,F)
    const float* z    = (const float*)d_in[1];   // (B,H)
    // d_in[2] = lengths (unused: all T)
    const float* Wih0 = (const float*)d_in[3];   // (4H,1)
    const float* Whh0 = (const float*)d_in[4];   // (4H,H)
    const float* bih0 = (const float*)d_in[5];
    const float* bhh0 = (const float*)d_in[6];
    const float* Wih1 = (const float*)d_in[7];   // (4H,H)
    const float* Whh1 = (const float*)d_in[8];   // (4H,H)
    const float* bih1 = (const float*)d_in[9];
    const float* bhh1 = (const float*)d_in[10];
    const float* Wout = (const float*)d_in[11];  // (1,H)
    const float* bout = (const float*)d_in[12];  // (1,)

    cudaFuncSetAttribute(lstm_kernel, cudaFuncAttributeMaxDynamicSharedMemorySize,
                         (int)sizeof(SmemLayout));

    init_kernel<<<(BSZ * HID + 255) / 256, 256>>>(z);
    lstm_kernel<<<NCTA, NTHREADS, sizeof(SmemLayout)>>>(
        seq, z, Wih0, Whh0, bih0, bhh0, Wih1, Whh1, bih1, bhh1, Wout, bout);
    finish_kernel<<<1, 1>>>((float*)d_out);
}

// round 12
// speedup vs baseline: 2.0911x; 2.0911x over previous
#include <cuda_runtime.h>
#include <cstdint>

// Problem constants
#define BSZ      256   // batch
#define TSTEPS   512   // time steps
#define HID      256   // hidden
#define GBGROUPS 8     // batch groups
#define GSLICES  16    // gate slices per group
#define NCTA     128   // GBGROUPS*GSLICES
#define BC       32    // batch per group
#define NU       16    // hidden units per slice per layer
#define NG       64    // gate rows per slice per layer (4*NU)
#define NTHREADS 128
#define WPAD     260   // weight row pad ([n][k] layout, k=256+4)
#define HPAD     132   // hT row pad ([m][k] layout, k=128+4)

// Persistent scratch (no cudaMalloc allowed) --------------------------------
__device__ float g_h0[2 * BSZ * HID];
__device__ float g_h1[2 * BSZ * HID];
__device__ float g_pp[BSZ * GSLICES];
__device__ float g_losspart[GBGROUPS];
__device__ int   g_bar[GBGROUPS];

struct SmemLayout {
    float w0 [NG * WPAD];   // Whh_l0 slice, [n][k] tf32      66.6KB
    float w1i[NG * WPAD];   // Wih_l1 slice, [n][k] tf32      66.6KB
    float w1h[NG * WPAD];   // Whh_l1 slice, [n][k] tf32      66.6KB
    float hT [32 * HPAD];   // staged h chunk [m][k] tf32     16.9KB
    float gbuf[BC * NG];    // gates tile 32x64 fp32           8KB
    float c0s [BC * NU];
    float c1s [BC * NU];
    float predvS[BC];
    float wih0 [NG];        // fp32 (exact)
    float bias0[NG];
    float bias1[NG];
    float woutS[NU];
    float lossS[BC];
    float boutv;
};

__device__ __forceinline__ float sigf(float x) {
    return 1.0f / (1.0f + __expf(-x));
}

__device__ __forceinline__ uint32_t to_tf32(float x) {
    uint32_t r;
    asm("cvt.rna.tf32.f32 %0, %1;" : "=r"(r) : "f"(x));
    return r;
}

__device__ __forceinline__ void bar_arrive(int g) {
    __threadfence();
    __syncthreads();
    if (threadIdx.x == 0) atomicAdd(&g_bar[g], 1);
}
__device__ __forceinline__ void bar_wait(int g, int target) {
    if (threadIdx.x == 0) {
        while (((volatile int*)g_bar)[g] < target) { __nanosleep(32); }
    }
    __syncthreads();
}

// Stage a 32x128 fp32 chunk of h (rows bbase..bbase+31, cols given by src
// pre-offset) into S.hT as tf32 bit patterns. Conflict-free STS.128.
__device__ __forceinline__ void stage_h(const float* __restrict__ src, int bbase,
                                        SmemLayout& S, int tid) {
    int w = tid >> 5, lane = tid & 31;
    #pragma unroll
    for (int mm = 0; mm < 8; ++mm) {
        int m = w * 8 + mm;
        float4 v = __ldcg(reinterpret_cast<const float4*>(src + (bbase + m) * HID) + lane);
        float4 o;
        o.x = __uint_as_float(to_tf32(v.x));
        o.y = __uint_as_float(to_tf32(v.y));
        o.z = __uint_as_float(to_tf32(v.z));
        o.w = __uint_as_float(to_tf32(v.w));
        *reinterpret_cast<float4*>(&S.hT[m * HPAD + lane * 4]) = o;
    }
}

// One 128-k chunk: C[32x64] += hT[32x128] * W^T  via tf32 mma.m16n8k8.
// Warp (wm,wn) owns rows wm*16..+15, cols wn*32..+31 (4 n-tiles of 8).
__device__ __forceinline__ void mma_chunk(const float* __restrict__ Wn,
                                          const SmemLayout& S,
                                          int arow, int g8, int tig, int wn,
                                          float acc[4][4]) {
    #pragma unroll
    for (int ks = 0; ks < 16; ++ks) {
        int kb = ks * 8;
        uint32_t a0 = __float_as_uint(S.hT[arow * HPAD + kb + tig]);
        uint32_t a1 = __float_as_uint(S.hT[(arow + 8) * HPAD + kb + tig]);
        uint32_t a2 = __float_as_uint(S.hT[arow * HPAD + kb + tig + 4]);
        uint32_t a3 = __float_as_uint(S.hT[(arow + 8) * HPAD + kb + tig + 4]);
        #pragma unroll
        for (int j = 0; j < 4; ++j) {
            int ncol = wn * 32 + j * 8 + g8;
            uint32_t b0 = __float_as_uint(Wn[ncol * WPAD + kb + tig]);
            uint32_t b1 = __float_as_uint(Wn[ncol * WPAD + kb + tig + 4]);
            asm volatile(
                "mma.sync.aligned.m16n8k8.row.col.f32.tf32.tf32.f32 "
                "{%0,%1,%2,%3}, {%4,%5,%6,%7}, {%8,%9}, {%0,%1,%2,%3};"
                : "+f"(acc[j][0]), "+f"(acc[j][1]), "+f"(acc[j][2]), "+f"(acc[j][3])
                : "r"(a0), "r"(a1), "r"(a2), "r"(a3), "r"(b0), "r"(b1));
        }
    }
}

__global__ void init_kernel(const float* __restrict__ z) {
    int t = blockIdx.x * blockDim.x + threadIdx.x;
    if (t < BSZ * HID) {
        float v = z[t];
        g_h0[t] = v;
        g_h1[t] = v;
    }
    if (t < BSZ * GSLICES) g_pp[t] = 0.0f;
    if (t < GBGROUPS) { g_bar[t] = 0; g_losspart[t] = 0.0f; }
}

__global__ __launch_bounds__(NTHREADS, 1)
void lstm_kernel(const float* __restrict__ seq,  const float* __restrict__ z,
                 const float* __restrict__ Wih0, const float* __restrict__ Whh0,
                 const float* __restrict__ bih0, const float* __restrict__ bhh0,
                 const float* __restrict__ Wih1, const float* __restrict__ Whh1,
                 const float* __restrict__ bih1, const float* __restrict__ bhh1,
                 const float* __restrict__ Wout, const float* __restrict__ boutp) {
    extern __shared__ __align__(16) char smraw[];
    SmemLayout& S = *reinterpret_cast<SmemLayout*>(smraw);

    const int tid   = threadIdx.x;
    const int g     = blockIdx.x / GSLICES;
    const int s     = blockIdx.x % GSLICES;
    const int bbase = g * BC;
    const int ubase = s * NU;

    // ---- one-time weight load, tf32-converted, [n][k] padded ----
    for (int idx = tid; idx < NG * HID; idx += NTHREADS) {
        int nl = idx >> 8, k = idx & 255;
        int grow = ((nl >> 4) << 8) + ubase + (nl & 15);
        S.w0 [nl * WPAD + k] = __uint_as_float(to_tf32(Whh0[grow * HID + k]));
        S.w1i[nl * WPAD + k] = __uint_as_float(to_tf32(Wih1[grow * HID + k]));
        S.w1h[nl * WPAD + k] = __uint_as_float(to_tf32(Whh1[grow * HID + k]));
    }
    for (int nl = tid; nl < NG; nl += NTHREADS) {
        int grow = ((nl >> 4) << 8) + ubase + (nl & 15);
        S.wih0 [nl] = Wih0[grow];
        S.bias0[nl] = bih0[grow] + bhh0[grow];
        S.bias1[nl] = bih1[grow] + bhh1[grow];
    }
    if (tid < NU)  S.woutS[tid] = Wout[ubase + tid];
    if (tid == 0)  S.boutv = boutp[0];
    for (int idx = tid; idx < BC * NU; idx += NTHREADS) {
        int m = idx >> 4, u = idx & 15;
        float v = z[(bbase + m) * HID + ubase + u];
        S.c0s[idx] = v;
        S.c1s[idx] = v;
    }
    __syncthreads();

    const int warp = tid >> 5, lane = tid & 31;
    const int wm = warp >> 1, wn = warp & 1;
    const int g8 = lane >> 2, tig = lane & 3;
    const int arow = wm * 16 + g8;
    const int u = tid & 15, mq = tid >> 4;
    float lossreg = 0.0f;

    for (int t = 0; t < TSTEPS; ++t) {
        const int cur = t & 1, nxt = cur ^ 1;
        float acc[4][4];

        // ==== layer-0 GEMM over h0_cur (no barrier dependence) ====
        #pragma unroll
        for (int j = 0; j < 4; ++j) {
            int col = wn * 32 + j * 8 + 2 * tig;
            acc[j][0] = S.bias0[col];
            acc[j][1] = S.bias0[col + 1];
            acc[j][2] = acc[j][0];
            acc[j][3] = acc[j][1];
        }
        const float* h0cur = &g_h0[cur * BSZ * HID];
        #pragma unroll
        for (int c = 0; c < 2; ++c) {
            stage_h(h0cur + c * 128, bbase, S, tid);
            __syncthreads();
            mma_chunk(&S.w0[c * 128], S, arow, g8, tig, wn, acc);
            __syncthreads();
        }

        // ==== wait barrier B(t-1): pred partials + h1_cur published ====
        bar_wait(g, t * 32);

        // ==== pred assembly + loss ====
        if (tid < BC) {
            float pv;
            if (t == 0) {
                pv = 0.0f;
            } else {
                pv = S.boutv;
                const float* pp = &g_pp[(bbase + tid) * GSLICES];
                #pragma unroll
                for (int q = 0; q < GSLICES; ++q) pv += __ldcg(pp + q);
            }
            S.predvS[tid] = pv;
            if (s == 0 && t > 0) {
                float d = __ldg(&seq[(bbase + tid) * TSTEPS + (t - 1)]) - pv;
                lossreg += d * d;
            }
        }
        __syncthreads();

        // ==== finish layer-0 gates: + pred * wih0 (exact fp32) ====
        {
            float p0 = S.predvS[wm * 16 + g8];
            float p1 = S.predvS[wm * 16 + g8 + 8];
            #pragma unroll
            for (int j = 0; j < 4; ++j) {
                int col = wn * 32 + j * 8 + 2 * tig;
                float wc0 = S.wih0[col], wc1 = S.wih0[col + 1];
                acc[j][0] += p0 * wc0;  acc[j][1] += p0 * wc1;
                acc[j][2] += p1 * wc0;  acc[j][3] += p1 * wc1;
                int row = wm * 16 + g8;
                *reinterpret_cast<float2*>(&S.gbuf[row * NG + col]) =
                    make_float2(acc[j][0], acc[j][1]);
                *reinterpret_cast<float2*>(&S.gbuf[(row + 8) * NG + col]) =
                    make_float2(acc[j][2], acc[j][3]);
            }
        }
        __syncthreads();

        // ==== layer-0 activations -> h0_nxt ====
        {
            float* h0nxt = &g_h0[nxt * BSZ * HID];
            #pragma unroll
            for (int r = 0; r < 4; ++r) {
                int m = mq * 4 + r;
                float gi = S.gbuf[m * NG + u];
                float gf = S.gbuf[m * NG + 16 + u];
                float gg = S.gbuf[m * NG + 32 + u];
                float go = S.gbuf[m * NG + 48 + u];
                float cv = S.c0s[m * NU + u];
                float cn = sigf(gf) * cv + sigf(gi) * tanhf(gg);
                float hn = sigf(go) * tanhf(cn);
                S.c0s[m * NU + u] = cn;
                h0nxt[(bbase + m) * HID + ubase + u] = hn;
            }
        }
        bar_arrive(g);   // barrier A(t) arrive (wait deferred)

        // ==== layer-1 GEMM: first the h1_cur half (no new barrier needed) ====
        #pragma unroll
        for (int j = 0; j < 4; ++j) {
            int col = wn * 32 + j * 8 + 2 * tig;
            acc[j][0] = S.bias1[col];
            acc[j][1] = S.bias1[col + 1];
            acc[j][2] = acc[j][0];
            acc[j][3] = acc[j][1];
        }
        const float* h1cur = &g_h1[cur * BSZ * HID];
        #pragma unroll
        for (int c = 0; c < 2; ++c) {
            stage_h(h1cur + c * 128, bbase, S, tid);
            __syncthreads();
            mma_chunk(&S.w1h[c * 128], S, arow, g8, tig, wn, acc);
            __syncthreads();
        }

        // ==== wait barrier A(t), then the h0_nxt half ====
        bar_wait(g, t * 32 + 16);
        const float* h0n = &g_h0[nxt * BSZ * HID];
        #pragma unroll
        for (int c = 0; c < 2; ++c) {
            stage_h(h0n + c * 128, bbase, S, tid);
            __syncthreads();
            mma_chunk(&S.w1i[c * 128], S, arow, g8, tig, wn, acc);
            __syncthreads();
        }

        // ==== write layer-1 gates ====
        #pragma unroll
        for (int j = 0; j < 4; ++j) {
            int col = wn * 32 + j * 8 + 2 * tig;
            int row = wm * 16 + g8;
            *reinterpret_cast<float2*>(&S.gbuf[row * NG + col]) =
                make_float2(acc[j][0], acc[j][1]);
            *reinterpret_cast<float2*>(&S.gbuf[(row + 8) * NG + col]) =
                make_float2(acc[j][2], acc[j][3]);
        }
        __syncthreads();

        // ==== layer-1 activations -> h1_nxt + fused pred partials ====
        {
            float* h1nxt = &g_h1[nxt * BSZ * HID];
            #pragma unroll
            for (int r = 0; r < 4; ++r) {
                int m = mq * 4 + r;
                float gi = S.gbuf[m * NG + u];
                float gf = S.gbuf[m * NG + 16 + u];
                float gg = S.gbuf[m * NG + 32 + u];
                float go = S.gbuf[m * NG + 48 + u];
                float cv = S.c1s[m * NU + u];
                float cn = sigf(gf) * cv + sigf(gi) * tanhf(gg);
                float hn = sigf(go) * tanhf(cn);
                S.c1s[m * NU + u] = cn;
                h1nxt[(bbase + m) * HID + ubase + u] = hn;
                // 16-lane reduction of hn * wout over u (deterministic)
                float v = hn * S.woutS[u];
                v += __shfl_down_sync(0xffffffffu, v, 8, 16);
                v += __shfl_down_sync(0xffffffffu, v, 4, 16);
                v += __shfl_down_sync(0xffffffffu, v, 2, 16);
                v += __shfl_down_sync(0xffffffffu, v, 1, 16);
                if (u == 0) g_pp[(bbase + m) * GSLICES + s] = v;
            }
        }
        bar_arrive(g);   // barrier B(t)
    }

    // ==== epilogue: final pred (step T) + loss ====
    bar_wait(g, TSTEPS * 32);
    if (tid < BC && s == 0) {
        float pv = S.boutv;
        const float* pp = &g_pp[(bbase + tid) * GSLICES];
        #pragma unroll
        for (int q = 0; q < GSLICES; ++q) pv += __ldcg(pp + q);
        float d = __ldg(&seq[(bbase + tid) * TSTEPS + (TSTEPS - 1)]) - pv;
        lossreg += d * d;
    }

    if (s == 0) {
        if (tid < BC) S.lossS[tid] = lossreg;
        __syncthreads();
        if (tid == 0) {
            float sum = 0.0f;
            for (int i = 0; i < BC; ++i) sum += S.lossS[i];
            g_losspart[g] = sum;
        }
    }
}

__global__ void finish_kernel(float* __restrict__ out) {
    float sum = 0.0f;
    for (int i = 0; i < GBGROUPS; ++i) sum += g_losspart[i];
    out[0] = sum / (float)(BSZ * TSTEPS);
}

extern "C" void kernel_launch(void* const* d_in, const int* in_sizes, int n_in,
                              void* d_out, int out_size) {
    const float* seq  = (const float*)d_in[0];
    const float* z    = (const float*)d_in[1];
    const float* Wih0 = (const float*)d_in[3];
    const float* Whh0 = (const float*)d_in[4];
    const float* bih0 = (const float*)d_in[5];
    const float* bhh0 = (const float*)d_in[6];
    const float* Wih1 = (const float*)d_in[7];
    const float* Whh1 = (const float*)d_in[8];
    const float* bih1 = (const float*)d_in[9];
    const float* bhh1 = (const float*)d_in[10];
    const float* Wout = (const float*)d_in[11];
    const float* bout = (const float*)d_in[12];

    cudaFuncSetAttribute(lstm_kernel, cudaFuncAttributeMaxDynamicSharedMemorySize,
                         (int)sizeof(SmemLayout));

    init_kernel<<<(BSZ * HID + 255) / 256, 256>>>(z);
    lstm_kernel<<<NCTA, NTHREADS, sizeof(SmemLayout)>>>(
        seq, z, Wih0, Whh0, bih0, bhh0, Wih1, Whh1, bih1, bhh1, Wout, bout);
    finish_kernel<<<1, 1>>>((float*)d_out);
}

// round 13
// speedup vs baseline: 3.0326x; 1.4502x over previous
#include <cuda_runtime.h>
#include <cuda_bf16.h>
#include <cstdint>

// Problem constants
#define BSZ      256
#define TSTEPS   512
#define HID      256
#define GBGROUPS 8
#define GSLICES  16
#define NCTA     128
#define BC       32
#define NU       16
#define NG       64
#define NTHREADS 128
#define HROW     136    // hT row stride in bf16 elems (128 + 8 pad) -> 68 words

// Persistent scratch ---------------------------------------------------------
__device__ unsigned short g_h0[2 * BSZ * HID];   // bf16 bits
__device__ unsigned short g_h1[2 * BSZ * HID];   // bf16 bits
__device__ float g_pp[BSZ * GSLICES];
__device__ float g_losspart[GBGROUPS];
__device__ int   g_bar[GBGROUPS];

// Shared memory --------------------------------------------------------------
// Weights pre-packed in m16n8k16 B-fragment order:
//   [wn:2][c:2][j:4][ks:8][lane:32][r:2][b:2]  (bf16), 16384 elems / matrix
struct SmemLayout {
    unsigned short w0 [16384];   // Whh_l0   32KB
    unsigned short w1h[16384];   // Whh_l1   32KB
    unsigned short w1i[16384];   // Wih_l1   32KB
    unsigned short hT [2][32 * HROW];  // double-buffered staged h  17KB
    float gbuf[BC * NG];
    float c0s [BC * NU];
    float c1s [BC * NU];
    float predvS[BC];
    float wih0 [NG];
    float bias0[NG];
    float bias1[NG];
    float woutS[NU];
    float lossS[BC];
    float boutv;
};

__device__ __forceinline__ float sigf(float x) { return 1.0f / (1.0f + __expf(-x)); }

__device__ __forceinline__ void bar_arrive(int g) {
    __threadfence();
    __syncthreads();
    if (threadIdx.x == 0) atomicAdd(&g_bar[g], 1);
}
__device__ __forceinline__ void bar_wait(int g, int target) {
    if (threadIdx.x == 0) {
        while (((volatile int*)g_bar)[g] < target) { __nanosleep(32); }
    }
    __syncthreads();
}

// LDG 32x128 bf16 chunk into registers (per-warp 8 rows, 2 rows/iter)
__device__ __forceinline__ void ldg_h(const unsigned short* __restrict__ src,
                                      int bbase, int w, int lane, uint4 pf[4]) {
    int half = lane >> 4, kq = lane & 15;
    #pragma unroll
    for (int it = 0; it < 4; ++it) {
        int m = w * 8 + it * 2 + half;
        pf[it] = __ldcg(reinterpret_cast<const uint4*>(src + (bbase + m) * HID) + kq);
    }
}
__device__ __forceinline__ void sts_h(unsigned short* __restrict__ buf,
                                      int w, int lane, const uint4 pf[4]) {
    int half = lane >> 4, kq = lane & 15;
    #pragma unroll
    for (int it = 0; it < 4; ++it) {
        int m = w * 8 + it * 2 + half;
        *reinterpret_cast<uint4*>(buf + m * HROW + kq * 8) = pf[it];
    }
}

// One 128-k chunk: acc[32x64 tile] += hT * W^T via bf16 mma.m16n8k16
__device__ __forceinline__ void mma_chunk(const unsigned short* __restrict__ wb,
                                          const unsigned short* __restrict__ hTb,
                                          int wm, int g8, int tig, int lane,
                                          float acc[4][4]) {
    const unsigned short* ap0 = hTb + (wm * 16 + g8) * HROW + tig * 2;
    #pragma unroll
    for (int ks = 0; ks < 8; ++ks) {
        const unsigned short* ap = ap0 + ks * 16;
        uint32_t a0 = *reinterpret_cast<const uint32_t*>(ap);
        uint32_t a1 = *reinterpret_cast<const uint32_t*>(ap + 8 * HROW);
        uint32_t a2 = *reinterpret_cast<const uint32_t*>(ap + 8);
        uint32_t a3 = *reinterpret_cast<const uint32_t*>(ap + 8 * HROW + 8);
        #pragma unroll
        for (int j = 0; j < 4; ++j) {
            uint2 bv = *reinterpret_cast<const uint2*>(wb + ((j * 8 + ks) * 32 + lane) * 4);
            asm volatile(
                "mma.sync.aligned.m16n8k16.row.col.f32.bf16.bf16.f32 "
                "{%0,%1,%2,%3}, {%4,%5,%6,%7}, {%8,%9}, {%0,%1,%2,%3};"
                : "+f"(acc[j][0]), "+f"(acc[j][1]), "+f"(acc[j][2]), "+f"(acc[j][3])
                : "r"(a0), "r"(a1), "r"(a2), "r"(a3), "r"(bv.x), "r"(bv.y));
        }
    }
}

__global__ void init_kernel(const float* __restrict__ z) {
    int t = blockIdx.x * blockDim.x + threadIdx.x;
    if (t < BSZ * HID) {
        unsigned short b = __bfloat16_as_ushort(__float2bfloat16(z[t]));
        g_h0[t] = b;
        g_h1[t] = b;
    }
    if (t < BSZ * GSLICES) g_pp[t] = 0.0f;
    if (t < GBGROUPS) { g_bar[t] = 0; g_losspart[t] = 0.0f; }
}

__global__ __launch_bounds__(NTHREADS, 1)
void lstm_kernel(const float* __restrict__ seq,  const float* __restrict__ z,
                 const float* __restrict__ Wih0, const float* __restrict__ Whh0,
                 const float* __restrict__ bih0, const float* __restrict__ bhh0,
                 const float* __restrict__ Wih1, const float* __restrict__ Whh1,
                 const float* __restrict__ bih1, const float* __restrict__ bhh1,
                 const float* __restrict__ Wout, const float* __restrict__ boutp) {
    extern __shared__ __align__(16) char smraw[];
    SmemLayout& S = *reinterpret_cast<SmemLayout*>(smraw);

    const int tid   = threadIdx.x;
    const int g     = blockIdx.x / GSLICES;
    const int s     = blockIdx.x % GSLICES;
    const int bbase = g * BC;
    const int ubase = s * NU;

    // ---- one-time weight load: convert to bf16, pack in B-fragment order ----
    for (int idx = tid; idx < NG * HID; idx += NTHREADS) {
        int nl = idx >> 8, k = idx & 255;
        int grow = ((nl >> 4) << 8) + ubase + (nl & 15);
        // fragment coordinates
        int wn = nl >> 5, g8d = nl & 7, j = (nl >> 3) & 3;
        int c = k >> 7, ks = (k >> 4) & 7, kk = k & 15;
        int r = kk >> 3, tg = (kk & 7) >> 1, b = kk & 1;
        int off = ((((wn * 2 + c) * 4 + j) * 8 + ks) * 32 + (g8d * 4 + tg)) * 4 + r * 2 + b;
        S.w0 [off] = __bfloat16_as_ushort(__float2bfloat16(Whh0[grow * HID + k]));
        S.w1h[off] = __bfloat16_as_ushort(__float2bfloat16(Whh1[grow * HID + k]));
        S.w1i[off] = __bfloat16_as_ushort(__float2bfloat16(Wih1[grow * HID + k]));
    }
    for (int nl = tid; nl < NG; nl += NTHREADS) {
        int grow = ((nl >> 4) << 8) + ubase + (nl & 15);
        S.wih0 [nl] = Wih0[grow];
        S.bias0[nl] = bih0[grow] + bhh0[grow];
        S.bias1[nl] = bih1[grow] + bhh1[grow];
    }
    if (tid < NU)  S.woutS[tid] = Wout[ubase + tid];
    if (tid == 0)  S.boutv = boutp[0];
    for (int idx = tid; idx < BC * NU; idx += NTHREADS) {
        int m = idx >> 4, u2 = idx & 15;
        float v = z[(bbase + m) * HID + ubase + u2];
        S.c0s[idx] = v;
        S.c1s[idx] = v;
    }
    __syncthreads();

    const int warp = tid >> 5, lane = tid & 31;
    const int wm = warp >> 1, wn = warp & 1;
    const int g8 = lane >> 2, tig = lane & 3;
    const int u = tid & 15, mq = tid >> 4;
    const unsigned short* w0b  = &S.w0 [wn * 2 * 4096];
    const unsigned short* w1hb = &S.w1h[wn * 2 * 4096];
    const unsigned short* w1ib = &S.w1i[wn * 2 * 4096];
    float lossreg = 0.0f;

    uint4 pf[4], pfN[4];
    ldg_h(&g_h0[0], bbase, warp, lane, pfN);   // prefetch L0 chunk0 for t=0

    for (int t = 0; t < TSTEPS; ++t) {
        const int cur = t & 1, nxt = cur ^ 1;
        const unsigned short* h0cur = &g_h0[cur * BSZ * HID];
        const unsigned short* h1cur = &g_h1[cur * BSZ * HID];
        float acc[4][4];

        // ===== layer-0 GEMM over h0_cur (pipelined) =====
        sts_h(S.hT[0], warp, lane, pfN);
        __syncthreads();
        ldg_h(h0cur + 128, bbase, warp, lane, pf);
        #pragma unroll
        for (int j = 0; j < 4; ++j) {
            int col = wn * 32 + j * 8 + 2 * tig;
            acc[j][0] = S.bias0[col];
            acc[j][1] = S.bias0[col + 1];
            acc[j][2] = acc[j][0];
            acc[j][3] = acc[j][1];
        }
        mma_chunk(w0b, S.hT[0], wm, g8, tig, lane, acc);
        sts_h(S.hT[1], warp, lane, pf);
        __syncthreads();
        mma_chunk(w0b + 4096, S.hT[1], wm, g8, tig, lane, acc);

        // ===== barrier B(t-1): pred partials + h1_cur published =====
        bar_wait(g, t * 32);
        if (tid < BC) {
            float pv;
            if (t == 0) {
                pv = 0.0f;
            } else {
                pv = S.boutv;
                const float* pp = &g_pp[(bbase + tid) * GSLICES];
                #pragma unroll
                for (int q = 0; q < GSLICES; ++q) pv += __ldcg(pp + q);
            }
            S.predvS[tid] = pv;
            if (s == 0 && t > 0) {
                float d = __ldg(&seq[(bbase + tid) * TSTEPS + (t - 1)]) - pv;
                lossreg += d * d;
            }
        }
        __syncthreads();

        ldg_h(h1cur, bbase, warp, lane, pf);   // safe after barrier B(t-1)

        // finish layer-0 gates: + pred * wih0 (exact fp32), write gbuf
        {
            float p0 = S.predvS[wm * 16 + g8];
            float p1 = S.predvS[wm * 16 + g8 + 8];
            #pragma unroll
            for (int j = 0; j < 4; ++j) {
                int col = wn * 32 + j * 8 + 2 * tig;
                float wc0 = S.wih0[col], wc1 = S.wih0[col + 1];
                int row = wm * 16 + g8;
                *reinterpret_cast<float2*>(&S.gbuf[row * NG + col]) =
                    make_float2(acc[j][0] + p0 * wc0, acc[j][1] + p0 * wc1);
                *reinterpret_cast<float2*>(&S.gbuf[(row + 8) * NG + col]) =
                    make_float2(acc[j][2] + p1 * wc0, acc[j][3] + p1 * wc1);
            }
        }
        __syncthreads();

        // layer-0 activations -> h0_nxt (bf16 global)
        {
            unsigned short* h0n = &g_h0[nxt * BSZ * HID];
            #pragma unroll
            for (int r = 0; r < 4; ++r) {
                int m = mq * 4 + r;
                float gi = S.gbuf[m * NG + u];
                float gf = S.gbuf[m * NG + 16 + u];
                float gg = S.gbuf[m * NG + 32 + u];
                float go = S.gbuf[m * NG + 48 + u];
                float cv = S.c0s[m * NU + u];
                float cn = sigf(gf) * cv + sigf(gi) * tanhf(gg);
                float hn = sigf(go) * tanhf(cn);
                S.c0s[m * NU + u] = cn;
                h0n[(bbase + m) * HID + ubase + u] = __bfloat16_as_ushort(__float2bfloat16(hn));
            }
        }
        bar_arrive(g);   // barrier A(t): h0_nxt published

        // ===== layer-1 GEMM: h1_cur half (pipelined) =====
        sts_h(S.hT[0], warp, lane, pf);
        __syncthreads();
        ldg_h(h1cur + 128, bbase, warp, lane, pf);
        #pragma unroll
        for (int j = 0; j < 4; ++j) {
            int col = wn * 32 + j * 8 + 2 * tig;
            acc[j][0] = S.bias1[col];
            acc[j][1] = S.bias1[col + 1];
            acc[j][2] = acc[j][0];
            acc[j][3] = acc[j][1];
        }
        mma_chunk(w1hb, S.hT[0], wm, g8, tig, lane, acc);
        sts_h(S.hT[1], warp, lane, pf);
        __syncthreads();
        mma_chunk(w1hb + 4096, S.hT[1], wm, g8, tig, lane, acc);

        // ===== barrier A(t), then h0_nxt half =====
        bar_wait(g, t * 32 + 16);
        const unsigned short* h0nv = &g_h0[nxt * BSZ * HID];
        ldg_h(h0nv, bbase, warp, lane, pf);
        sts_h(S.hT[0], warp, lane, pf);
        __syncthreads();
        ldg_h(h0nv + 128, bbase, warp, lane, pf);
        mma_chunk(w1ib, S.hT[0], wm, g8, tig, lane, acc);
        sts_h(S.hT[1], warp, lane, pf);
        __syncthreads();
        ldg_h(h0nv, bbase, warp, lane, pfN);   // prefetch next step's L0 chunk0
        mma_chunk(w1ib + 4096, S.hT[1], wm, g8, tig, lane, acc);

        // write layer-1 gates
        #pragma unroll
        for (int j = 0; j < 4; ++j) {
            int col = wn * 32 + j * 8 + 2 * tig;
            int row = wm * 16 + g8;
            *reinterpret_cast<float2*>(&S.gbuf[row * NG + col]) =
                make_float2(acc[j][0], acc[j][1]);
            *reinterpret_cast<float2*>(&S.gbuf[(row + 8) * NG + col]) =
                make_float2(acc[j][2], acc[j][3]);
        }
        __syncthreads();

        // layer-1 activations -> h1_nxt + fused pred partials
        {
            unsigned short* h1n = &g_h1[nxt * BSZ * HID];
            #pragma unroll
            for (int r = 0; r < 4; ++r) {
                int m = mq * 4 + r;
                float gi = S.gbuf[m * NG + u];
                float gf = S.gbuf[m * NG + 16 + u];
                float gg = S.gbuf[m * NG + 32 + u];
                float go = S.gbuf[m * NG + 48 + u];
                float cv = S.c1s[m * NU + u];
                float cn = sigf(gf) * cv + sigf(gi) * tanhf(gg);
                float hn = sigf(go) * tanhf(cn);
                S.c1s[m * NU + u] = cn;
                h1n[(bbase + m) * HID + ubase + u] = __bfloat16_as_ushort(__float2bfloat16(hn));
                float v = hn * S.woutS[u];
                v += __shfl_down_sync(0xffffffffu, v, 8, 16);
                v += __shfl_down_sync(0xffffffffu, v, 4, 16);
                v += __shfl_down_sync(0xffffffffu, v, 2, 16);
                v += __shfl_down_sync(0xffffffffu, v, 1, 16);
                if (u == 0) g_pp[(bbase + m) * GSLICES + s] = v;
            }
        }
        bar_arrive(g);   // barrier B(t)
    }

    // ===== epilogue: final pred + loss =====
    bar_wait(g, TSTEPS * 32);
    if (tid < BC && s == 0) {
        float pv = S.boutv;
        const float* pp = &g_pp[(bbase + tid) * GSLICES];
        #pragma unroll
        for (int q = 0; q < GSLICES; ++q) pv += __ldcg(pp + q);
        float d = __ldg(&seq[(bbase + tid) * TSTEPS + (TSTEPS - 1)]) - pv;
        lossreg += d * d;
    }
    if (s == 0) {
        if (tid < BC) S.lossS[tid] = lossreg;
        __syncthreads();
        if (tid == 0) {
            float sum = 0.0f;
            for (int i = 0; i < BC; ++i) sum += S.lossS[i];
            g_losspart[g] = sum;
        }
    }
}

__global__ void finish_kernel(float* __restrict__ out) {
    float sum = 0.0f;
    for (int i = 0; i < GBGROUPS; ++i) sum += g_losspart[i];
    out[0] = sum / (float)(BSZ * TSTEPS);
}

extern "C" void kernel_launch(void* const* d_in, const int* in_sizes, int n_in,
                              void* d_out, int out_size) {
    const float* seq  = (const float*)d_in[0];
    const float* z    = (const float*)d_in[1];
    const float* Wih0 = (const float*)d_in[3];
    const float* Whh0 = (const float*)d_in[4];
    const float* bih0 = (const float*)d_in[5];
    const float* bhh0 = (const float*)d_in[6];
    const float* Wih1 = (const float*)d_in[7];
    const float* Whh1 = (const float*)d_in[8];
    const float* bih1 = (const float*)d_in[9];
    const float* bhh1 = (const float*)d_in[10];
    const float* Wout = (const float*)d_in[11];
    const float* bout = (const float*)d_in[12];

    cudaFuncSetAttribute(lstm_kernel, cudaFuncAttributeMaxDynamicSharedMemorySize,
                         (int)sizeof(SmemLayout));

    init_kernel<<<(BSZ * HID + 255) / 256, 256>>>(z);
    lstm_kernel<<<NCTA, NTHREADS, sizeof(SmemLayout)>>>(
        seq, z, Wih0, Whh0, bih0, bhh0, Wih1, Whh1, bih1, bhh1, Wout, bout);
    finish_kernel<<<1, 1>>>((float*)d_out);
}